// round 2
// baseline (speedup 1.0000x reference)
#include <cuda_runtime.h>
#include <math.h>

#define B_ 64
#define T_ 1024
#define D_ 256
#define H_ 512
#define O_ 256

#define GROUPS 16
#define CPG 8              // CTAs per group (column split of H)
#define BPG (B_ / GROUPS)  // 4 batches per group
#define COLS (H_ / CPG)    // 64 output columns per CTA
#define WSTRIDE 516        // padded row stride for W slice in SMEM (conflict-free LDS.128)

// Scratch (static device allocations; in-kernel_launch alloc is forbidden)
__device__ float    g_xw[(size_t)B_ * T_ * H_];   // 128 MB: xW0, later reused as xW1
__device__ float    g_seq[(size_t)B_ * T_ * H_];  // 128 MB: layer-0 outputs
__device__ float    g_h[2][B_][H_];               // double-buffered hidden exchange
// Self-resetting barrier state: cnt returns to 0 after each barrier; phase flips
// an even number of times per launch (1024 per scan x 2 scans) -> state identical
// at launch end, so graph replays are deterministic with NO init kernel.
__device__ unsigned g_cnt[GROUPS];
__device__ unsigned g_phase[GROUPS];

__device__ __forceinline__ unsigned f2tf32(float f) {
    unsigned r;
    asm("cvt.rna.tf32.f32 %0, %1;" : "=r"(r) : "f"(f));
    return r;
}

__device__ __forceinline__ void mma_tf32(float* c, unsigned a0, unsigned a1,
                                         unsigned a2, unsigned a3,
                                         unsigned b0, unsigned b1) {
    asm volatile(
        "mma.sync.aligned.m16n8k8.row.col.f32.tf32.tf32.f32 "
        "{%0,%1,%2,%3}, {%4,%5,%6,%7}, {%8,%9}, {%0,%1,%2,%3};\n"
        : "+f"(c[0]), "+f"(c[1]), "+f"(c[2]), "+f"(c[3])
        : "r"(a0), "r"(a1), "r"(a2), "r"(a3), "r"(b0), "r"(b1));
}

// ---------------------------------------------------------------------------
// C[M,N] = A[M,K] @ B[N,K]^T + bias1[N] + bias2[N]   (tf32 tensor cores)
// 128x128 block tile, BK=32, 256 threads, warp tile 32x64 (m16n8k8).
// M,N multiples of 128; K multiple of 32 (all uses satisfy this).
// ---------------------------------------------------------------------------
__global__ void __launch_bounds__(256) gemm_tf32(
    const float* __restrict__ A, const float* __restrict__ Bm,
    const float* __restrict__ b1, const float* __restrict__ b2,
    float* __restrict__ C, int M, int N, int K)
{
    __shared__ unsigned Asm[128 * 36];
    __shared__ unsigned Bsm[128 * 36];

    const int m0 = blockIdx.y * 128;
    const int n0 = blockIdx.x * 128;
    const int tid = threadIdx.x;
    const int lane = tid & 31;
    const int wid = tid >> 5;
    const int wm = wid & 3;    // 4 warp rows  (32 M each)
    const int wn = wid >> 2;   // 2 warp cols  (64 N each)
    const int l4 = lane >> 2;
    const int lm = lane & 3;

    float acc[2][8][4];
#pragma unroll
    for (int i = 0; i < 2; i++)
#pragma unroll
        for (int j = 0; j < 8; j++)
#pragma unroll
            for (int k = 0; k < 4; k++) acc[i][j][k] = 0.f;

    for (int k0 = 0; k0 < K; k0 += 32) {
#pragma unroll
        for (int i = 0; i < 4; i++) {
            int qg = tid + 256 * i;      // 1024 float4 slots = 128 rows x 8 quads
            int row = qg >> 3;
            int q = qg & 7;
            float4 va = *(const float4*)(A + (size_t)(m0 + row) * K + k0 + q * 4);
            unsigned* da = &Asm[row * 36 + q * 4];
            da[0] = f2tf32(va.x); da[1] = f2tf32(va.y);
            da[2] = f2tf32(va.z); da[3] = f2tf32(va.w);
            float4 vb = *(const float4*)(Bm + (size_t)(n0 + row) * K + k0 + q * 4);
            unsigned* db = &Bsm[row * 36 + q * 4];
            db[0] = f2tf32(vb.x); db[1] = f2tf32(vb.y);
            db[2] = f2tf32(vb.z); db[3] = f2tf32(vb.w);
        }
        __syncthreads();

#pragma unroll
        for (int ks = 0; ks < 4; ks++) {
            unsigned a[2][4];
#pragma unroll
            for (int mt = 0; mt < 2; mt++) {
                const unsigned* ap = &Asm[(wm * 32 + mt * 16 + l4) * 36 + ks * 8 + lm];
                a[mt][0] = ap[0];
                a[mt][1] = ap[8 * 36];
                a[mt][2] = ap[4];
                a[mt][3] = ap[8 * 36 + 4];
            }
#pragma unroll
            for (int nt = 0; nt < 8; nt++) {
                const unsigned* bp = &Bsm[(wn * 64 + nt * 8 + l4) * 36 + ks * 8 + lm];
                unsigned b0 = bp[0];
                unsigned b1v = bp[4];
                mma_tf32(acc[0][nt], a[0][0], a[0][1], a[0][2], a[0][3], b0, b1v);
                mma_tf32(acc[1][nt], a[1][0], a[1][1], a[1][2], a[1][3], b0, b1v);
            }
        }
        __syncthreads();
    }

#pragma unroll
    for (int nt = 0; nt < 8; nt++) {
        int n = n0 + wn * 64 + nt * 8 + 2 * lm;
        float bv0 = b1[n] + b2[n];
        float bv1 = b1[n + 1] + b2[n + 1];
#pragma unroll
        for (int mt = 0; mt < 2; mt++) {
            int r = m0 + wm * 32 + mt * 16 + l4;
            float2 v0 = make_float2(acc[mt][nt][0] + bv0, acc[mt][nt][1] + bv1);
            float2 v1 = make_float2(acc[mt][nt][2] + bv0, acc[mt][nt][3] + bv1);
            *(float2*)(C + (size_t)r * N + n) = v0;
            *(float2*)(C + (size_t)(r + 8) * N + n) = v1;
        }
    }
}

// ---------------------------------------------------------------------------
// Persistent recurrent scan.  Grid = GROUPS*CPG = 128 CTAs, 256 threads.
// CTA (g,c): batches [g*4, g*4+4), output columns [c*64, c*64+64).
// W_hh slice (64 rows x 512) held in SMEM, h exchanged via g_h + group barrier.
// FUSE_FC: after the final step, hb holds h_T for the group's batches -> fc here.
// ---------------------------------------------------------------------------
#define SCAN_SMEM_FLOATS (COLS * WSTRIDE + BPG * H_ + 4 * 256)
#define SCAN_SMEM_BYTES  (SCAN_SMEM_FLOATS * 4)

template <bool STORE_SEQ, bool FUSE_FC>
__global__ void __launch_bounds__(256) scan_kernel(
    const float* __restrict__ Whh,
    const float* __restrict__ Wfc, const float* __restrict__ bfc,
    float* __restrict__ out)
{
    extern __shared__ float sm[];
    float* Wt   = sm;                       // [COLS][WSTRIDE]
    float* hb   = sm + COLS * WSTRIDE;      // [BPG][H_]
    float* part = hb + BPG * H_;            // [4][256]

    const int g = blockIdx.x >> 3;
    const int c = blockIdx.x & 7;
    const int tid = threadIdx.x;

    // Load W slice: rows c*64 .. c*64+63 of W_hh (coalesced)
    for (int i = tid; i < COLS * H_; i += 256) {
        int r = i >> 9;
        int k = i & (H_ - 1);
        Wt[r * WSTRIDE + k] = Whh[(size_t)(c * COLS + r) * H_ + k];
    }
    for (int i = tid; i < BPG * H_; i += 256) hb[i] = 0.f;  // h0 = 0
    __syncthreads();

    const int c_loc = tid & 63;   // GEMM mapping: column
    const int kg    = tid >> 6;   // GEMM mapping: K-slice (4 x 128)
    const int ob    = tid >> 6;   // reduce mapping: batch
    const int oj    = tid & 63;   // reduce mapping: column
    const int bglob = g * BPG + ob;
    const int jglob = c * COLS + oj;

    const float* xwp = g_xw + (size_t)bglob * T_ * H_ + jglob;
    const float4* w4 = (const float4*)(Wt + c_loc * WSTRIDE + kg * 128);

    unsigned phase = 0;
    volatile unsigned* ph = &g_phase[g];

    for (int t = 0; t < T_; t++) {
        // streamed input projection for this step (hidden under the GEMM below)
        float xw_r = __ldcg(xwp + (size_t)t * H_);

        const float4* h40 = (const float4*)(hb + 0 * H_ + kg * 128);
        const float4* h41 = (const float4*)(hb + 1 * H_ + kg * 128);
        const float4* h42 = (const float4*)(hb + 2 * H_ + kg * 128);
        const float4* h43 = (const float4*)(hb + 3 * H_ + kg * 128);

        float a0 = 0.f, a1 = 0.f, a2 = 0.f, a3 = 0.f;
#pragma unroll 8
        for (int q = 0; q < 32; q++) {
            float4 w = w4[q];
            float4 v0 = h40[q];
            a0 += w.x * v0.x + w.y * v0.y + w.z * v0.z + w.w * v0.w;
            float4 v1 = h41[q];
            a1 += w.x * v1.x + w.y * v1.y + w.z * v1.z + w.w * v1.w;
            float4 v2 = h42[q];
            a2 += w.x * v2.x + w.y * v2.y + w.z * v2.z + w.w * v2.w;
            float4 v3 = h43[q];
            a3 += w.x * v3.x + w.y * v3.y + w.z * v3.z + w.w * v3.w;
        }
        part[kg * 256 +   0 + c_loc] = a0;
        part[kg * 256 +  64 + c_loc] = a1;
        part[kg * 256 + 128 + c_loc] = a2;
        part[kg * 256 + 192 + c_loc] = a3;
        __syncthreads();

        float s = part[tid] + part[256 + tid] + part[512 + tid] + part[768 + tid] + xw_r;
        float hn = tanhf(s);

        const int p = t & 1;
        __stcg(&g_h[p][bglob][jglob], hn);
        if (STORE_SEQ) __stcg(&g_seq[((size_t)bglob * T_ + t) * H_ + jglob], hn);

        // ---- group barrier (sense-reversal, self-resetting) ----
        __threadfence();
        __syncthreads();
        unsigned want = phase ^ 1u;
        if (tid == 0) {
            unsigned old = atomicAdd(&g_cnt[g], 1u);
            if (old == CPG - 1) {
                *(volatile unsigned*)&g_cnt[g] = 0u;
                __threadfence();
                atomicExch(&g_phase[g], want);
            } else {
                while (*ph != want) { }
            }
        }
        __syncthreads();
        phase = want;

        // reload full group hidden state for next step (L2, bypass L1)
        const float4* src = (const float4*)(&g_h[p][g * BPG][0]);
        float4* dst = (float4*)hb;
#pragma unroll
        for (int i = 0; i < (BPG * H_ / 4) / 256; i++)
            dst[tid + 256 * i] = __ldcg(src + tid + 256 * i);
        __syncthreads();
    }

    if (FUSE_FC) {
        // hb now holds h_T for the group's 4 batches (full H).
        // CTA c computes output columns [c*32, c*32+32) for those batches.
        if (tid < 128) {
            int b = tid >> 5;
            int nl = tid & 31;
            int n = c * (O_ / CPG) + nl;
            const float4* h4 = (const float4*)(hb + b * H_);
            const float4* wf = (const float4*)(Wfc + (size_t)n * H_);
            float acc = 0.f;
#pragma unroll 8
            for (int q = 0; q < H_ / 4; q++) {
                float4 a = wf[q];
                float4 x = h4[q];
                acc += a.x * x.x + a.y * x.y + a.z * x.z + a.w * x.w;
            }
            out[(g * BPG + b) * O_ + n] = acc + bfc[n];
        }
    }
}

// ---------------------------------------------------------------------------

extern "C" void kernel_launch(void* const* d_in, const int* in_sizes, int n_in,
                              void* d_out, int out_size)
{
    const float* x     = (const float*)d_in[0];
    const float* W_ih0 = (const float*)d_in[1];
    const float* W_hh0 = (const float*)d_in[2];
    const float* b_ih0 = (const float*)d_in[3];
    const float* b_hh0 = (const float*)d_in[4];
    const float* W_ih1 = (const float*)d_in[5];
    const float* W_hh1 = (const float*)d_in[6];
    const float* b_ih1 = (const float*)d_in[7];
    const float* b_hh1 = (const float*)d_in[8];
    const float* W_fc  = (const float*)d_in[9];
    const float* b_fc  = (const float*)d_in[10];
    float* out = (float*)d_out;

    void* p_xw = nullptr;
    void* p_seq = nullptr;
    cudaGetSymbolAddress(&p_xw, g_xw);
    cudaGetSymbolAddress(&p_seq, g_seq);

    cudaFuncSetAttribute(scan_kernel<true, false>,
                         cudaFuncAttributeMaxDynamicSharedMemorySize, SCAN_SMEM_BYTES);
    cudaFuncSetAttribute(scan_kernel<false, true>,
                         cudaFuncAttributeMaxDynamicSharedMemorySize, SCAN_SMEM_BYTES);

    const int MT = B_ * T_;  // 65536

    // Layer 0 input projection: g_xw = x @ W_ih0^T + b_ih0 + b_hh0
    gemm_tf32<<<dim3(H_ / 128, MT / 128), 256>>>(
        x, W_ih0, b_ih0, b_hh0, (float*)p_xw, MT, H_, D_);

    // Layer 0 scan -> g_seq
    scan_kernel<true, false><<<GROUPS * CPG, 256, SCAN_SMEM_BYTES>>>(
        W_hh0, nullptr, nullptr, nullptr);

    // Layer 1 input projection: g_xw = g_seq @ W_ih1^T + b_ih1 + b_hh1
    gemm_tf32<<<dim3(H_ / 128, MT / 128), 256>>>(
        (const float*)p_seq, W_ih1, b_ih1, b_hh1, (float*)p_xw, MT, H_, H_);

    // Layer 1 scan + fused fc -> out
    scan_kernel<false, true><<<GROUPS * CPG, 256, SCAN_SMEM_BYTES>>>(
        W_hh1, W_fc, b_fc, out);
}